// round 1
// baseline (speedup 1.0000x reference)
#include <cuda_runtime.h>
#include <cstdint>

#define NMAX   50000
#define EMAX   500000
#define ZDIM   136      // 16 (he) x 8 (xe) + 8 (xe bias lane)
#define ZVEC   34       // ZDIM/4
#define GRAPHS 64
#define EPS    1e-5f

// ---------------- scratch (device globals; no allocation allowed) ----------------
__device__ float4   g_Zagg4[(size_t)NMAX * ZVEC];   // [N,136] z aggregation
__device__ float    g_deg[NMAX];
__device__ float    g_pre[(size_t)NMAX * 64];       // NNConv pre-BN output
__device__ float    g_colsum[64];
__device__ float    g_colsq[64];
__device__ float    g_gsum[GRAPHS * 64];
__device__ unsigned g_gmax[GRAPHS * 64];            // float-as-uint max (relu'd vals >= 0)
__device__ float    g_gcnt[GRAPHS];
__device__ float    g_gfeat[GRAPHS * 128];
__device__ float    g_y1[GRAPHS * 256];
__device__ float    g_y2[GRAPHS * 128];
__device__ float    g_y3[GRAPHS * 64];

// ---------------- zero scratch ----------------
__global__ void k_zero(int nzagg4, int n) {
    int i = blockIdx.x * blockDim.x + threadIdx.x;
    int stride = gridDim.x * blockDim.x;
    float4 z4 = make_float4(0.f, 0.f, 0.f, 0.f);
    for (int j = i; j < nzagg4; j += stride) g_Zagg4[j] = z4;
    for (int j = i; j < n; j += stride) g_deg[j] = 0.f;
    if (i < 64) { g_colsum[i] = 0.f; g_colsq[i] = 0.f; }
    if (i < GRAPHS * 64) { g_gsum[i] = 0.f; g_gmax[i] = 0u; }
    if (i < GRAPHS) g_gcnt[i] = 0.f;
}

// ---------------- edge kernel: scatter z_e into Zagg[dst] ----------------
__global__ void k_edge(const float* __restrict__ x,
                       const int* __restrict__ ei,
                       const float* __restrict__ ea,
                       const float* __restrict__ w_e1,
                       const float* __restrict__ b_e1,
                       int E) {
    __shared__ float sW1[128];   // [t][j] = w_e1[t*16+j]
    __shared__ float sB1[16];
    if (threadIdx.x < 128) sW1[threadIdx.x] = w_e1[threadIdx.x];
    if (threadIdx.x < 16)  sB1[threadIdx.x] = b_e1[threadIdx.x];
    __syncthreads();

    int e = blockIdx.x * blockDim.x + threadIdx.x;
    if (e >= E) return;

    int src = __ldg(&ei[e]);
    int dst = __ldg(&ei[E + e]);

    float4 ea0 = __ldg((const float4*)(ea + (size_t)e * 8));
    float4 ea1 = __ldg((const float4*)(ea + (size_t)e * 8 + 4));
    float eav[8] = { ea0.x, ea0.y, ea0.z, ea0.w, ea1.x, ea1.y, ea1.z, ea1.w };

    float he[16];
    #pragma unroll
    for (int j = 0; j < 16; j++) {
        float s = sB1[j];
        #pragma unroll
        for (int t = 0; t < 8; t++) s = fmaf(eav[t], sW1[t * 16 + j], s);
        he[j] = fmaxf(s, 0.f);
    }

    float4 xe0 = __ldg((const float4*)(x + (size_t)src * 8));
    float4 xe1 = __ldg((const float4*)(x + (size_t)src * 8 + 4));

    float4* zr = &g_Zagg4[(size_t)dst * ZVEC];
    #pragma unroll
    for (int j = 0; j < 16; j++) {
        float h = he[j];
        atomicAdd(zr + j * 2,     make_float4(h * xe0.x, h * xe0.y, h * xe0.z, h * xe0.w));
        atomicAdd(zr + j * 2 + 1, make_float4(h * xe1.x, h * xe1.y, h * xe1.z, h * xe1.w));
    }
    atomicAdd(zr + 32, xe0);
    atomicAdd(zr + 33, xe1);
    atomicAdd(&g_deg[dst], 1.f);
}

// ---------------- node kernel: agg = Zagg@Wc/deg + x@root + bias; BN partial stats ----------------
__global__ void k_node(const float* __restrict__ x,
                       const float* __restrict__ w_e2,
                       const float* __restrict__ b_e2,
                       const float* __restrict__ root,
                       const float* __restrict__ cbias,
                       int N) {
    __shared__ float2 sWc[ZDIM][32];   // sWc[k][l] = (Wc[k][2l], Wc[k][2l+1])
    __shared__ float2 sRoot[8][32];
    __shared__ float  sCB[64];
    __shared__ float2 redS[8][32];
    __shared__ float2 redQ[8][32];

    int tid = threadIdx.x;
    for (int idx = tid; idx < ZDIM * 32; idx += blockDim.x) {
        int k = idx >> 5, l = idx & 31;
        int h0 = 2 * l;
        float a, b;
        if (k < 128) {
            int j = k >> 3, f = k & 7;
            a = w_e2[j * 512 + f * 64 + h0];
            b = w_e2[j * 512 + f * 64 + h0 + 1];
        } else {
            int f = k - 128;
            a = b_e2[f * 64 + h0];
            b = b_e2[f * 64 + h0 + 1];
        }
        sWc[k][l] = make_float2(a, b);
    }
    for (int idx = tid; idx < 8 * 32; idx += blockDim.x) {
        int f = idx >> 5, l = idx & 31;
        sRoot[f][l] = make_float2(root[f * 64 + 2 * l], root[f * 64 + 2 * l + 1]);
    }
    if (tid < 64) sCB[tid] = cbias[tid];
    __syncthreads();

    int warp = tid >> 5, lane = tid & 31;
    int nbase = (blockIdx.x * 8 + warp) * 4;

    int  nn[4];
    bool valid[4];
    #pragma unroll
    for (int i = 0; i < 4; i++) {
        int n = nbase + i;
        valid[i] = (n < N);
        nn[i] = valid[i] ? n : 0;
    }

    const float4* zr0 = &g_Zagg4[(size_t)nn[0] * ZVEC];
    const float4* zr1 = &g_Zagg4[(size_t)nn[1] * ZVEC];
    const float4* zr2 = &g_Zagg4[(size_t)nn[2] * ZVEC];
    const float4* zr3 = &g_Zagg4[(size_t)nn[3] * ZVEC];

    float2 agg[4];
    #pragma unroll
    for (int i = 0; i < 4; i++) agg[i] = make_float2(0.f, 0.f);

    #pragma unroll 2
    for (int kk = 0; kk < ZVEC; kk++) {
        float4 z0 = __ldg(zr0 + kk);
        float4 z1 = __ldg(zr1 + kk);
        float4 z2 = __ldg(zr2 + kk);
        float4 z3 = __ldg(zr3 + kk);
        float2 wa = sWc[4 * kk + 0][lane];
        float2 wb = sWc[4 * kk + 1][lane];
        float2 wc = sWc[4 * kk + 2][lane];
        float2 wd = sWc[4 * kk + 3][lane];
        agg[0].x = fmaf(z0.x, wa.x, agg[0].x); agg[0].y = fmaf(z0.x, wa.y, agg[0].y);
        agg[0].x = fmaf(z0.y, wb.x, agg[0].x); agg[0].y = fmaf(z0.y, wb.y, agg[0].y);
        agg[0].x = fmaf(z0.z, wc.x, agg[0].x); agg[0].y = fmaf(z0.z, wc.y, agg[0].y);
        agg[0].x = fmaf(z0.w, wd.x, agg[0].x); agg[0].y = fmaf(z0.w, wd.y, agg[0].y);
        agg[1].x = fmaf(z1.x, wa.x, agg[1].x); agg[1].y = fmaf(z1.x, wa.y, agg[1].y);
        agg[1].x = fmaf(z1.y, wb.x, agg[1].x); agg[1].y = fmaf(z1.y, wb.y, agg[1].y);
        agg[1].x = fmaf(z1.z, wc.x, agg[1].x); agg[1].y = fmaf(z1.z, wc.y, agg[1].y);
        agg[1].x = fmaf(z1.w, wd.x, agg[1].x); agg[1].y = fmaf(z1.w, wd.y, agg[1].y);
        agg[2].x = fmaf(z2.x, wa.x, agg[2].x); agg[2].y = fmaf(z2.x, wa.y, agg[2].y);
        agg[2].x = fmaf(z2.y, wb.x, agg[2].x); agg[2].y = fmaf(z2.y, wb.y, agg[2].y);
        agg[2].x = fmaf(z2.z, wc.x, agg[2].x); agg[2].y = fmaf(z2.z, wc.y, agg[2].y);
        agg[2].x = fmaf(z2.w, wd.x, agg[2].x); agg[2].y = fmaf(z2.w, wd.y, agg[2].y);
        agg[3].x = fmaf(z3.x, wa.x, agg[3].x); agg[3].y = fmaf(z3.x, wa.y, agg[3].y);
        agg[3].x = fmaf(z3.y, wb.x, agg[3].x); agg[3].y = fmaf(z3.y, wb.y, agg[3].y);
        agg[3].x = fmaf(z3.z, wc.x, agg[3].x); agg[3].y = fmaf(z3.z, wc.y, agg[3].y);
        agg[3].x = fmaf(z3.w, wd.x, agg[3].x); agg[3].y = fmaf(z3.w, wd.y, agg[3].y);
    }

    float2 ls = make_float2(0.f, 0.f), lq = make_float2(0.f, 0.f);
    #pragma unroll
    for (int i = 0; i < 4; i++) {
        float2 p = make_float2(sCB[2 * lane], sCB[2 * lane + 1]);
        const float* xr = x + (size_t)nn[i] * 8;
        #pragma unroll
        for (int f = 0; f < 8; f++) {
            float xv = __ldg(xr + f);
            float2 rw = sRoot[f][lane];
            p.x = fmaf(xv, rw.x, p.x);
            p.y = fmaf(xv, rw.y, p.y);
        }
        float invd = 1.f / fmaxf(__ldg(&g_deg[nn[i]]), 1.f);
        p.x = fmaf(agg[i].x, invd, p.x);
        p.y = fmaf(agg[i].y, invd, p.y);
        if (valid[i]) {
            g_pre[(size_t)nn[i] * 64 + 2 * lane]     = p.x;
            g_pre[(size_t)nn[i] * 64 + 2 * lane + 1] = p.y;
            ls.x += p.x; ls.y += p.y;
            lq.x = fmaf(p.x, p.x, lq.x);
            lq.y = fmaf(p.y, p.y, lq.y);
        }
    }
    redS[warp][lane] = ls;
    redQ[warp][lane] = lq;
    __syncthreads();
    if (tid < 32) {
        float2 S = make_float2(0.f, 0.f), Q = make_float2(0.f, 0.f);
        #pragma unroll
        for (int w = 0; w < 8; w++) {
            S.x += redS[w][tid].x; S.y += redS[w][tid].y;
            Q.x += redQ[w][tid].x; Q.y += redQ[w][tid].y;
        }
        atomicAdd(&g_colsum[2 * tid],     S.x);
        atomicAdd(&g_colsum[2 * tid + 1], S.y);
        atomicAdd(&g_colsq[2 * tid],      Q.x);
        atomicAdd(&g_colsq[2 * tid + 1],  Q.y);
    }
}

// ---------------- BN + relu + per-graph pooling (run-length compressed atomics) ----------------
__global__ void k_bnpool(const int* __restrict__ batch,
                         const float* __restrict__ gam,
                         const float* __restrict__ bet,
                         int N) {
    __shared__ float sScale[64], sShift[64];
    int tid = threadIdx.x;
    if (tid < 64) {
        float invN = 1.f / (float)N;
        float m = g_colsum[tid] * invN;
        float v = g_colsq[tid] * invN - m * m;
        float r = rsqrtf(v + EPS);
        float sc = r * gam[tid];
        sScale[tid] = sc;
        sShift[tid] = bet[tid] - m * sc;
    }
    __syncthreads();

    int c = tid & 63;
    int chunk = blockIdx.x * 4 + (tid >> 6);
    int n0 = chunk * 32;
    if (n0 >= N) return;
    int nend = min(n0 + 32, N);
    float sc = sScale[c], sh = sShift[c];

    int gcur = -1;
    float s = 0.f, mx = 0.f;
    int cnt = 0;
    for (int n = n0; n < nend; n++) {
        int g = __ldg(&batch[n]);
        if (g != gcur) {
            if (gcur >= 0) {
                atomicAdd(&g_gsum[gcur * 64 + c], s);
                atomicMax(&g_gmax[gcur * 64 + c], __float_as_uint(mx));
                if (c == 0) atomicAdd(&g_gcnt[gcur], (float)cnt);
            }
            gcur = g; s = 0.f; mx = 0.f; cnt = 0;
        }
        float p = __ldg(&g_pre[(size_t)n * 64 + c]);
        float h = fmaxf(fmaf(p, sc, sh), 0.f);
        s += h;
        mx = fmaxf(mx, h);
        cnt++;
    }
    if (gcur >= 0) {
        atomicAdd(&g_gsum[gcur * 64 + c], s);
        atomicMax(&g_gmax[gcur * 64 + c], __float_as_uint(mx));
        if (c == 0) atomicAdd(&g_gcnt[gcur], (float)cnt);
    }
}

// ---------------- graph feature assembly [G,128] = concat(mean, max) ----------------
__global__ void k_gfeat() {
    int i = blockIdx.x * blockDim.x + threadIdx.x;
    if (i >= GRAPHS * 128) return;
    int g = i >> 7, c = i & 127;
    float v;
    if (c < 64) v = g_gsum[g * 64 + c] / fmaxf(g_gcnt[g], 1.f);
    else        v = __uint_as_float(g_gmax[g * 64 + (c - 64)]);
    g_gfeat[i] = v;
}

// ---------------- fused linear + BN(over 64 rows) + relu; block owns 32 output cols ----------------
__global__ void k_layer(const float* __restrict__ in,   // [64, I]
                        const float* __restrict__ w,    // [I, O]
                        const float* __restrict__ b,
                        const float* __restrict__ gam,
                        const float* __restrict__ bet,
                        float* __restrict__ out,        // [64, O]
                        int I, int O) {
    extern __shared__ float sIn[];                       // 64*I floats
    __shared__ float redS[8][32], redQ[8][32];
    __shared__ float sScale[32], sShift[32];

    int tid = threadIdx.x;
    for (int idx = tid; idx < 64 * I; idx += blockDim.x) sIn[idx] = in[idx];
    __syncthreads();

    int c = tid & 31, r0 = tid >> 5;
    int cg = blockIdx.x * 32 + c;

    float acc[8];
    float bv = __ldg(&b[cg]);
    #pragma unroll
    for (int i = 0; i < 8; i++) acc[i] = bv;

    for (int k = 0; k < I; k++) {
        float wv = __ldg(&w[k * O + cg]);
        #pragma unroll
        for (int i = 0; i < 8; i++)
            acc[i] = fmaf(sIn[(r0 + 8 * i) * I + k], wv, acc[i]);
    }

    float s = 0.f, q = 0.f;
    #pragma unroll
    for (int i = 0; i < 8; i++) { s += acc[i]; q = fmaf(acc[i], acc[i], q); }
    redS[r0][c] = s;
    redQ[r0][c] = q;
    __syncthreads();
    if (tid < 32) {
        float S = 0.f, Q = 0.f;
        #pragma unroll
        for (int w8 = 0; w8 < 8; w8++) { S += redS[w8][tid]; Q += redQ[w8][tid]; }
        float m = S * (1.f / 64.f);
        float v = Q * (1.f / 64.f) - m * m;
        float r = rsqrtf(v + EPS);
        float sc = r * __ldg(&gam[blockIdx.x * 32 + tid]);
        sScale[tid] = sc;
        sShift[tid] = __ldg(&bet[blockIdx.x * 32 + tid]) - m * sc;
    }
    __syncthreads();
    float sc = sScale[c], sh = sShift[c];
    #pragma unroll
    for (int i = 0; i < 8; i++)
        out[(r0 + 8 * i) * O + cg] = fmaxf(fmaf(acc[i], sc, sh), 0.f);
}

// ---------------- final projection [64,64]@[64,10] ----------------
__global__ void k_out(const float* __restrict__ wout,
                      const float* __restrict__ bout,
                      float* __restrict__ out) {
    int t = threadIdx.x;
    if (t >= 640) return;
    int g = t / 10, o = t % 10;
    float s = __ldg(&bout[o]);
    #pragma unroll
    for (int k = 0; k < 64; k++)
        s = fmaf(g_y3[g * 64 + k], __ldg(&wout[k * 10 + o]), s);
    out[t] = s;
}

// ---------------- launch ----------------
extern "C" void kernel_launch(void* const* d_in, const int* in_sizes, int n_in,
                              void* d_out, int out_size) {
    const float* x      = (const float*)d_in[0];
    const int*   ei     = (const int*)  d_in[1];
    const float* ea     = (const float*)d_in[2];
    const int*   batch  = (const int*)  d_in[3];
    const float* w_e1   = (const float*)d_in[4];
    const float* b_e1   = (const float*)d_in[5];
    const float* w_e2   = (const float*)d_in[6];
    const float* b_e2   = (const float*)d_in[7];
    const float* root   = (const float*)d_in[8];
    const float* cbias  = (const float*)d_in[9];
    const float* g_bnc  = (const float*)d_in[10];
    const float* b_bnc  = (const float*)d_in[11];
    const float* w1     = (const float*)d_in[12];
    const float* b1     = (const float*)d_in[13];
    const float* g1     = (const float*)d_in[14];
    const float* be1    = (const float*)d_in[15];
    const float* w2     = (const float*)d_in[16];
    const float* b2     = (const float*)d_in[17];
    const float* g2     = (const float*)d_in[18];
    const float* be2    = (const float*)d_in[19];
    const float* w3     = (const float*)d_in[20];
    const float* b3     = (const float*)d_in[21];
    const float* g3     = (const float*)d_in[22];
    const float* be3    = (const float*)d_in[23];
    const float* wout   = (const float*)d_in[24];
    const float* bout   = (const float*)d_in[25];

    int N = in_sizes[0] / 8;
    int E = in_sizes[2] / 8;
    if (N > NMAX) N = NMAX;
    if (E > EMAX) E = EMAX;

    void *p_gfeat, *p_y1, *p_y2, *p_y3;
    cudaGetSymbolAddress(&p_gfeat, g_gfeat);
    cudaGetSymbolAddress(&p_y1, g_y1);
    cudaGetSymbolAddress(&p_y2, g_y2);
    cudaGetSymbolAddress(&p_y3, g_y3);

    cudaFuncSetAttribute(k_layer, cudaFuncAttributeMaxDynamicSharedMemorySize,
                         64 * 256 * (int)sizeof(float));

    k_zero<<<1024, 256>>>(N * ZVEC, N);
    k_edge<<<(E + 255) / 256, 256>>>(x, ei, ea, w_e1, b_e1, E);
    k_node<<<(N + 31) / 32, 256>>>(x, w_e2, b_e2, root, cbias, N);
    int chunks = (N + 31) / 32;
    k_bnpool<<<(chunks + 3) / 4, 256>>>(batch, g_bnc, b_bnc, N);
    k_gfeat<<<(GRAPHS * 128 + 255) / 256, 256>>>();
    k_layer<<<8, 256, 64 * 128 * sizeof(float)>>>((const float*)p_gfeat, w1, b1, g1, be1, (float*)p_y1, 128, 256);
    k_layer<<<4, 256, 64 * 256 * sizeof(float)>>>((const float*)p_y1,    w2, b2, g2, be2, (float*)p_y2, 256, 128);
    k_layer<<<2, 256, 64 * 128 * sizeof(float)>>>((const float*)p_y2,    w3, b3, g3, be3, (float*)p_y3, 128, 64);
    k_out<<<1, 640>>>(wout, bout, (float*)d_out);
}